// round 5
// baseline (speedup 1.0000x reference)
#include <cuda_runtime.h>
#include <cuda_bf16.h>
#include <cstdint>

#define BATCH   16
#define NQ      576
#define DIM     1024
#define HID     4096
#define HEADS   8
#define DHEAD   128
#define ROWS    (BATCH*NQ)        // 9216
#define BHCNT   (BATCH*HEADS)     // 128

// ---------------- device scratch (no allocations allowed) ----------------
__device__ float g_kv[ROWS*DIM];
__device__ float g_kvpos[ROWS*DIM];
__device__ float g_qn[NQ*DIM];
__device__ float g_qp[NQ*DIM];
__device__ float g_kp[ROWS*DIM];
__device__ float g_vp[ROWS*DIM];
__device__ float g_sc[(size_t)BHCNT*NQ*NQ];   // 42.5M floats
__device__ float g_ctx[ROWS*DIM];
__device__ float g_attn[ROWS*DIM];
__device__ float g_h[(size_t)ROWS*HID];       // 37.7M floats
__device__ float g_gates[ROWS*2];
// tf32-pre-rounded operand copies
__device__ float g_xr[ROWS*DIM];
__device__ float g_w1r[(size_t)HID*DIM];
__device__ float g_w2r[(size_t)HID*HID];
__device__ float g_ipwr[(size_t)3*DIM*DIM];
__device__ float g_outwr[(size_t)DIM*DIM];

// ---------------- small helpers ----------------
__device__ __forceinline__ float warp_sum(float v){
    #pragma unroll
    for (int o=16;o;o>>=1) v += __shfl_xor_sync(0xffffffffu, v, o);
    return v;
}
__device__ __forceinline__ float softplusf(float x){
    return log1pf(expf(-fabsf(x))) + fmaxf(x, 0.f);
}
__device__ __forceinline__ float gelu_f(float x){
    return 0.5f * x * (1.0f + erff(x * 0.7071067811865475f));
}
__device__ __forceinline__ uint32_t f2tf(float x){
    uint32_t r; asm("cvt.rna.tf32.f32 %0, %1;" : "=r"(r) : "f"(x)); return r;
}
__device__ __forceinline__ float roundtf(float x){ return __uint_as_float(f2tf(x)); }
__device__ __forceinline__ void mma_tf32(float* c, const uint32_t* a, const uint32_t* b){
    asm volatile(
      "mma.sync.aligned.m16n8k8.row.col.f32.tf32.tf32.f32 "
      "{%0,%1,%2,%3}, {%4,%5,%6,%7}, {%8,%9}, {%0,%1,%2,%3};\n"
      : "+f"(c[0]), "+f"(c[1]), "+f"(c[2]), "+f"(c[3])
      : "r"(a[0]), "r"(a[1]), "r"(a[2]), "r"(a[3]), "r"(b[0]), "r"(b[1]));
}
__device__ __forceinline__ void cp_async16(void* smem, const void* gmem, int sz){
    uint32_t s = (uint32_t)__cvta_generic_to_shared(smem);
    asm volatile("cp.async.ca.shared.global [%0], [%1], 16, %2;\n"
                 :: "r"(s), "l"(gmem), "r"(sz));
}
__device__ __forceinline__ void cp_commit(){ asm volatile("cp.async.commit_group;\n"); }
__device__ __forceinline__ void cp_wait1(){ asm volatile("cp.async.wait_group 1;\n"); }

// ---------------- pre-round copy (fp32 -> tf32-rounded fp32) ----------------
__global__ void round_copy_kernel(const float4* __restrict__ in,
                                  float4* __restrict__ out, int n4)
{
    int i = blockIdx.x*blockDim.x + threadIdx.x;
    int stride = gridDim.x*blockDim.x;
    for (; i < n4; i += stride){
        float4 v = in[i];
        v.x = roundtf(v.x); v.y = roundtf(v.y);
        v.z = roundtf(v.z); v.w = roundtf(v.w);
        out[i] = v;
    }
}

// ---------------- LN(x) + pos + gating (fused: one read of x) ----------------
__global__ void ln_x_kernel(const float* __restrict__ x,
                            const float* __restrict__ g, const float* __restrict__ b,
                            const float* __restrict__ pos,
                            const float* __restrict__ wg, const float* __restrict__ wn,
                            const float* __restrict__ noise,
                            float* __restrict__ kv, float* __restrict__ kvpos,
                            float* __restrict__ gates)
{
    int row = blockIdx.x;
    int c   = row % NQ;
    const float* xr = x + (size_t)row*DIM;
    int t = threadIdx.x;
    float v[4];
    float s=0.f, ss=0.f, d0=0.f, d1=0.f, d2=0.f, d3=0.f;
    #pragma unroll
    for (int i=0;i<4;i++){
        int k = t + i*256;
        float xv = xr[k];
        v[i]=xv; s+=xv; ss+=xv*xv;
        d0 += xv*wg[k*2+0]; d1 += xv*wg[k*2+1];
        d2 += xv*wn[k*2+0]; d3 += xv*wn[k*2+1];
    }
    s  = warp_sum(s);  ss = warp_sum(ss);
    d0 = warp_sum(d0); d1 = warp_sum(d1);
    d2 = warp_sum(d2); d3 = warp_sum(d3);
    __shared__ float red[8][6];
    __shared__ float bc[2];
    int warp = t>>5, lane = t&31;
    if (lane==0){
        red[warp][0]=s; red[warp][1]=ss; red[warp][2]=d0;
        red[warp][3]=d1; red[warp][4]=d2; red[warp][5]=d3;
    }
    __syncthreads();
    if (t==0){
        float S=0,SS=0,D0=0,D1=0,D2=0,D3=0;
        #pragma unroll
        for (int w=0;w<8;w++){
            S+=red[w][0]; SS+=red[w][1]; D0+=red[w][2];
            D1+=red[w][3]; D2+=red[w][4]; D3+=red[w][5];
        }
        float mean = S * (1.f/DIM);
        float var  = SS * (1.f/DIM) - mean*mean;
        bc[0]=mean; bc[1]=rsqrtf(var + 1e-5f);
        float std0 = softplusf(D2) + 0.01f;
        float std1 = softplusf(D3) + 0.01f;
        float z0 = D0 + noise[(size_t)row*2+0]*std0;
        float z1 = D1 + noise[(size_t)row*2+1]*std1;
        float mz = fmaxf(z0,z1);
        float e0 = expf(z0-mz), e1 = expf(z1-mz);
        float l0 = e0/(e0+e1), l1 = e1/(e0+e1);
        float sm = l0 + l1;
        gates[(size_t)row*2+0] = l0/(sm+1e-6f);
        gates[(size_t)row*2+1] = l1/(sm+1e-6f);
    }
    __syncthreads();
    float mean = bc[0], inv = bc[1];
    #pragma unroll
    for (int i=0;i<4;i++){
        int k = t + i*256;
        float lnv = (v[i]-mean)*inv*g[k] + b[k];
        kv[(size_t)row*DIM + k]    = roundtf(lnv);
        kvpos[(size_t)row*DIM + k] = roundtf(lnv + pos[(size_t)c*DIM + k]);
    }
}

// ---------------- LN(query) + pos ----------------
__global__ void ln_q_kernel(const float* __restrict__ q,
                            const float* __restrict__ g, const float* __restrict__ b,
                            const float* __restrict__ pos, float* __restrict__ out)
{
    int row = blockIdx.x;
    const float* qr = q + (size_t)row*DIM;
    int t = threadIdx.x;
    float v[4];
    float s=0.f, ss=0.f;
    #pragma unroll
    for (int i=0;i<4;i++){
        int k = t + i*256;
        float xv = qr[k];
        v[i]=xv; s+=xv; ss+=xv*xv;
    }
    s = warp_sum(s); ss = warp_sum(ss);
    __shared__ float red[8][2];
    __shared__ float bc[2];
    int warp=t>>5, lane=t&31;
    if (lane==0){ red[warp][0]=s; red[warp][1]=ss; }
    __syncthreads();
    if (t==0){
        float S=0,SS=0;
        #pragma unroll
        for (int w=0;w<8;w++){ S+=red[w][0]; SS+=red[w][1]; }
        float mean = S*(1.f/DIM);
        float var  = SS*(1.f/DIM) - mean*mean;
        bc[0]=mean; bc[1]=rsqrtf(var+1e-5f);
    }
    __syncthreads();
    float mean=bc[0], inv=bc[1];
    #pragma unroll
    for (int i=0;i<4;i++){
        int k = t + i*256;
        out[(size_t)row*DIM + k] =
            roundtf((v[i]-mean)*inv*g[k] + b[k] + pos[(size_t)row*DIM + k]);
    }
}

// ---------------- row softmax over 576 cols (scale folded in) ----------------
__global__ void softmax_kernel(float* __restrict__ s){
    int warp = threadIdx.x>>5, lane = threadIdx.x&31;
    size_t row = (size_t)blockIdx.x*8 + warp;
    float* p = s + row*NQ;
    float v[18];
    float m = -1e30f;
    #pragma unroll
    for (int i=0;i<18;i++){ v[i] = p[lane + i*32]; m = fmaxf(m, v[i]); }
    #pragma unroll
    for (int o=16;o;o>>=1) m = fmaxf(m, __shfl_xor_sync(0xffffffffu, m, o));
    float sum = 0.f;
    const float SCALE = 0.08838834764831845f;   // 1/sqrt(128)
    #pragma unroll
    for (int i=0;i<18;i++){ v[i] = __expf((v[i]-m)*SCALE); sum += v[i]; }
    #pragma unroll
    for (int o=16;o;o>>=1) sum += __shfl_xor_sync(0xffffffffu, sum, o);
    float inv = 1.f/sum;
    #pragma unroll
    for (int i=0;i<18;i++) p[lane + i*32] = roundtf(v[i]*inv);
}

// ---------------- generic tf32 GEMM: C = epi(A(M,K) * B^T + bias) ----------------
// Inputs are PRE-ROUNDED to tf32 values in gmem; mainloop feeds raw bits to mma.
// 3-stage cp.async pipeline. BT==0: B is (N,K) row-major (TN). BT==1: (K,N) (NN).
// EPI: 0=none 1=+bias 2=gelu(+bias) 3=g0*(+bias) write 4=+= g1*(+bias)
// EPI<=2 outputs feed later GEMMs -> stores tf32-rounded.
#define BMT 128
#define BNT 128
#define BKT 16
#define KPAD 20
#define STAGES 3
#define SMEM_BYTES (STAGES*(BMT+BNT)*KPAD*4)

template<int BT>
__device__ __forceinline__ void load_tile(
    float (*As)[KPAD], float (*Bs)[KPAD],
    const float* __restrict__ A, const float* __restrict__ Bm,
    int lda, int ldb, int m0, int n0, int M, int N, int k0, int tid)
{
    #pragma unroll
    for (int i=0;i<2;i++){
        int id = tid + i*256;
        int r = id >> 2, c4 = (id & 3)*4;
        int gr = m0 + r;
        int sz = (gr < M) ? 16 : 0;
        const float* src = A + (size_t)(gr < M ? gr : 0)*lda + k0 + c4;
        cp_async16(&As[r][c4], src, sz);
    }
    if (BT == 0){
        #pragma unroll
        for (int i=0;i<2;i++){
            int id = tid + i*256;
            int r = id >> 2, c4 = (id & 3)*4;
            int gr = n0 + r;
            int sz = (gr < N) ? 16 : 0;
            const float* src = Bm + (size_t)(gr < N ? gr : 0)*ldb + k0 + c4;
            cp_async16(&Bs[r][c4], src, sz);
        }
    } else {
        #pragma unroll
        for (int i=0;i<8;i++){
            int id = tid + i*256;
            int n = id & 127, k = id >> 7;
            int gn = n0 + n;
            float vv = 0.f;
            if (gn < N) vv = Bm[(size_t)(k0+k)*ldb + gn];
            Bs[n][k] = vv;
        }
    }
}

__device__ __forceinline__ void mma_compute(
    const float (*as)[KPAD], const float (*bs)[KPAD],
    float acc[4][4][4], int wm, int wn, int group, int tig)
{
    #pragma unroll
    for (int ks=0; ks<2; ks++){
        int kk = ks*8;
        uint32_t af[4][4], bf[4][2];
        #pragma unroll
        for (int mf=0; mf<4; mf++){
            int rA = wm*64 + mf*16;
            af[mf][0] = __float_as_uint(as[rA+group  ][kk+tig  ]);
            af[mf][1] = __float_as_uint(as[rA+group+8][kk+tig  ]);
            af[mf][2] = __float_as_uint(as[rA+group  ][kk+tig+4]);
            af[mf][3] = __float_as_uint(as[rA+group+8][kk+tig+4]);
        }
        #pragma unroll
        for (int nf=0; nf<4; nf++){
            int cB = wn*32 + nf*8;
            bf[nf][0] = __float_as_uint(bs[cB+group][kk+tig  ]);
            bf[nf][1] = __float_as_uint(bs[cB+group][kk+tig+4]);
        }
        #pragma unroll
        for (int mf=0; mf<4; mf++)
            #pragma unroll
            for (int nf=0; nf<4; nf++)
                mma_tf32(acc[mf][nf], af[mf], bf[nf]);
    }
}

template<int EPI, int BT>
__global__ void __launch_bounds__(256,2) gemm_kernel(
    const float* __restrict__ A, int lda, long long aSB, long long aSH,
    const float* __restrict__ Bm, int ldb, long long bSB, long long bSH,
    const float* __restrict__ bias,
    float* __restrict__ C, int ldc, long long cSB, long long cSH,
    int M, int N, int K, int nh,
    const float* __restrict__ gates)
{
    extern __shared__ float smemf[];
    float (*As)[BMT][KPAD] = reinterpret_cast<float(*)[BMT][KPAD]>(smemf);
    float (*Bs)[BNT][KPAD] =
        reinterpret_cast<float(*)[BNT][KPAD]>(smemf + STAGES*BMT*KPAD);

    int z = blockIdx.z;
    int hh = z % nh, bb = z / nh;
    A  += (size_t)bb*aSB + (size_t)hh*aSH;
    Bm += (size_t)bb*bSB + (size_t)hh*bSH;
    C  += (size_t)bb*cSB + (size_t)hh*cSH;
    int m0 = blockIdx.y*BMT, n0 = blockIdx.x*BNT;
    int tid = threadIdx.x;
    int warp = tid>>5, lane = tid&31;
    int wm = warp & 1, wn = warp >> 1;
    int group = lane>>5 ? 0 : (lane>>2), tig = lane&3;
    int nK = K / BKT;

    float acc[4][4][4];
    #pragma unroll
    for (int a_=0;a_<4;a_++)
        #pragma unroll
        for (int b_=0;b_<4;b_++)
            #pragma unroll
            for (int c_=0;c_<4;c_++) acc[a_][b_][c_] = 0.f;

    // prologue: stage 0 and 1 in flight
    load_tile<BT>(As[0], Bs[0], A, Bm, lda, ldb, m0, n0, M, N, 0, tid);
    cp_commit();
    load_tile<BT>(As[1], Bs[1], A, Bm, lda, ldb, m0, n0, M, N, BKT, tid);
    cp_commit();

    int st = 0;           // stage being computed
    int wst = 2;          // stage being written next
    for (int kt=0; kt<nK; kt++){
        cp_wait1();
        __syncthreads();
        if (kt+2 < nK)
            load_tile<BT>(As[wst], Bs[wst], A, Bm, lda, ldb,
                          m0, n0, M, N, (kt+2)*BKT, tid);
        cp_commit();
        mma_compute(As[st], Bs[st], acc, wm, wn, group, tig);
        st = (st+1 == STAGES) ? 0 : st+1;
        wst = (wst+1 == STAGES) ? 0 : wst+1;
    }

    // epilogue
    #pragma unroll
    for (int mf=0; mf<4; mf++){
        #pragma unroll
        for (int half=0; half<2; half++){
            int r = m0 + wm*64 + mf*16 + group + half*8;
            if (r >= M) continue;
            float gv = 0.f;
            if (EPI==3) gv = gates[(size_t)r*2+0];
            if (EPI==4) gv = gates[(size_t)r*2+1];
            #pragma unroll
            for (int nf=0; nf<4; nf++){
                int col = n0 + wn*32 + nf*8 + tig*2;
                if (col >= N) continue;
                float v0 = acc[mf][nf][half*2+0];
                float v1 = acc[mf][nf][half*2+1];
                if (EPI >= 1){ v0 += bias[col]; v1 += bias[col+1]; }
                if (EPI == 2){ v0 = gelu_f(v0); v1 = gelu_f(v1); }
                float2* dst = reinterpret_cast<float2*>(C + (size_t)r*ldc + col);
                if (EPI == 3){ v0 *= gv; v1 *= gv; }
                if (EPI == 4){ float2 o = *dst; v0 = o.x + gv*v0; v1 = o.y + gv*v1; }
                if (EPI <= 2){ v0 = roundtf(v0); v1 = roundtf(v1); }
                float2 st2; st2.x = v0; st2.y = v1;
                *dst = st2;
            }
        }
    }
}

// ---------------- host launcher ----------------
extern "C" void kernel_launch(void* const* d_in, const int* in_sizes, int n_in,
                              void* d_out, int out_size)
{
    const float* x     = (const float*)d_in[0];
    const float* noise = (const float*)d_in[1];
    const float* W1    = (const float*)d_in[2];
    const float* b1    = (const float*)d_in[3];
    const float* W2    = (const float*)d_in[4];
    const float* b2    = (const float*)d_in[5];
    const float* query = (const float*)d_in[6];
    const float* pos   = (const float*)d_in[7];
    const float* lnqg  = (const float*)d_in[8];
    const float* lnqb  = (const float*)d_in[9];
    const float* lnkg  = (const float*)d_in[10];
    const float* lnkb  = (const float*)d_in[11];
    const float* ipw   = (const float*)d_in[12];
    const float* ipb   = (const float*)d_in[13];
    const float* outw  = (const float*)d_in[14];
    const float* outb  = (const float*)d_in[15];
    const float* wg    = (const float*)d_in[16];
    const float* wn    = (const float*)d_in[17];
    float* out = (float*)d_out;

    float *kv,*kvpos,*qn,*qp,*kp,*vp,*sc,*ctx,*attn,*hbuf,*gates;
    float *xr,*w1r,*w2r,*ipwr,*outwr;
    cudaGetSymbolAddress((void**)&kv,    g_kv);
    cudaGetSymbolAddress((void**)&kvpos, g_kvpos);
    cudaGetSymbolAddress((void**)&qn,    g_qn);
    cudaGetSymbolAddress((void**)&qp,    g_qp);
    cudaGetSymbolAddress((void**)&kp,    g_kp);
    cudaGetSymbolAddress((void**)&vp,    g_vp);
    cudaGetSymbolAddress((void**)&sc,    g_sc);
    cudaGetSymbolAddress((void**)&ctx,   g_ctx);
    cudaGetSymbolAddress((void**)&attn,  g_attn);
    cudaGetSymbolAddress((void**)&hbuf,  g_h);
    cudaGetSymbolAddress((void**)&gates, g_gates);
    cudaGetSymbolAddress((void**)&xr,    g_xr);
    cudaGetSymbolAddress((void**)&w1r,   g_w1r);
    cudaGetSymbolAddress((void**)&w2r,   g_w2r);
    cudaGetSymbolAddress((void**)&ipwr,  g_ipwr);
    cudaGetSymbolAddress((void**)&outwr, g_outwr);

    // opt-in to 60KB dynamic smem for every gemm instantiation (idempotent)
    cudaFuncSetAttribute(gemm_kernel<0,0>, cudaFuncAttributeMaxDynamicSharedMemorySize, SMEM_BYTES);
    cudaFuncSetAttribute(gemm_kernel<0,1>, cudaFuncAttributeMaxDynamicSharedMemorySize, SMEM_BYTES);
    cudaFuncSetAttribute(gemm_kernel<1,0>, cudaFuncAttributeMaxDynamicSharedMemorySize, SMEM_BYTES);
    cudaFuncSetAttribute(gemm_kernel<2,0>, cudaFuncAttributeMaxDynamicSharedMemorySize, SMEM_BYTES);
    cudaFuncSetAttribute(gemm_kernel<3,0>, cudaFuncAttributeMaxDynamicSharedMemorySize, SMEM_BYTES);
    cudaFuncSetAttribute(gemm_kernel<4,0>, cudaFuncAttributeMaxDynamicSharedMemorySize, SMEM_BYTES);

    const long long SBH = (long long)NQ*NQ;           // 331776
    const long long SBB = (long long)HEADS*NQ*NQ;     // 2654208
    const long long KVB = (long long)NQ*DIM;          // 589824

    // 0) pre-round static operands to tf32 values
    round_copy_kernel<<<2048,256>>>((const float4*)x,   (float4*)xr,   ROWS*DIM/4);
    round_copy_kernel<<<2048,256>>>((const float4*)W1,  (float4*)w1r,  HID*DIM/4);
    round_copy_kernel<<<4096,256>>>((const float4*)W2,  (float4*)w2r,  (int)((size_t)HID*HID/4));
    round_copy_kernel<<<2048,256>>>((const float4*)ipw, (float4*)ipwr, 3*DIM*DIM/4);
    round_copy_kernel<<<1024,256>>>((const float4*)outw,(float4*)outwr,DIM*DIM/4);

    // 1) LN(x) + pos + gating ; LN(query) + pos   (stores tf32-rounded)
    ln_x_kernel<<<ROWS, 256>>>(x, lnkg, lnkb, pos, wg, wn, noise, kv, kvpos, gates);
    ln_q_kernel<<<NQ, 256>>>(query, lnqg, lnqb, pos, qn);

    // 2) QKV projections
    gemm_kernel<1,0><<<dim3(8,5,1),256,SMEM_BYTES>>>(qn,DIM,0,0, ipwr,DIM,0,0, ipb,
                                          qp,DIM,0,0, NQ,DIM,DIM, 1, nullptr);
    gemm_kernel<1,0><<<dim3(8,72,1),256,SMEM_BYTES>>>(kvpos,DIM,0,0, ipwr+(size_t)DIM*DIM,DIM,0,0, ipb+DIM,
                                           kp,DIM,0,0, ROWS,DIM,DIM, 1, nullptr);
    gemm_kernel<1,0><<<dim3(8,72,1),256,SMEM_BYTES>>>(kv,DIM,0,0, ipwr+(size_t)2*DIM*DIM,DIM,0,0, ipb+2*DIM,
                                           vp,DIM,0,0, ROWS,DIM,DIM, 1, nullptr);

    // 3) attention: scores = qp @ kp^T (per batch*head), softmax, ctx = P @ vp
    gemm_kernel<0,0><<<dim3(5,5,BHCNT),256,SMEM_BYTES>>>(qp,DIM,0,DHEAD, kp,DIM,KVB,DHEAD, nullptr,
                                              sc,NQ, SBB,SBH, NQ,NQ,DHEAD, HEADS, nullptr);
    softmax_kernel<<<(BHCNT*NQ)/8, 256>>>(sc);
    gemm_kernel<0,1><<<dim3(1,5,BHCNT),256,SMEM_BYTES>>>(sc,NQ, SBB,SBH, vp,DIM,KVB,DHEAD, nullptr,
                                              ctx,DIM, KVB,DHEAD, NQ,DHEAD,NQ, HEADS, nullptr);

    // 4) attention output projection
    gemm_kernel<1,0><<<dim3(8,72,1),256,SMEM_BYTES>>>(ctx,DIM,0,0, outwr,DIM,0,0, outb,
                                           attn,DIM,0,0, ROWS,DIM,DIM, 1, nullptr);

    // 5) expert 0: gelu(x@W1^T+b1) @ W2^T + b2, scaled by g0 -> out
    gemm_kernel<2,0><<<dim3(32,72,1),256,SMEM_BYTES>>>(xr,DIM,0,0, w1r,DIM,0,0, b1,
                                            hbuf,HID,0,0, ROWS,HID,DIM, 1, nullptr);
    gemm_kernel<3,0><<<dim3(32,72,1),256,SMEM_BYTES>>>(hbuf,HID,0,0, w2r,HID,0,0, b2,
                                            out,HID,0,0, ROWS,HID,HID, 1, gates);

    // 6) expert 1: gelu(attn@W1^T+b1) @ W2^T + b2, scaled by g1, += out
    gemm_kernel<2,0><<<dim3(32,72,1),256,SMEM_BYTES>>>(attn,DIM,0,0, w1r,DIM,0,0, b1,
                                            hbuf,HID,0,0, ROWS,HID,DIM, 1, nullptr);
    gemm_kernel<4,0><<<dim3(32,72,1),256,SMEM_BYTES>>>(hbuf,HID,0,0, w2r,HID,0,0, b2,
                                            out,HID,0,0, ROWS,HID,HID, 1, gates);
}

// round 7
// speedup vs baseline: 1.5164x; 1.5164x over previous
#include <cuda_runtime.h>
#include <cuda_bf16.h>
#include <cstdint>

#define BATCH   16
#define NQ      576
#define DIM     1024
#define HID     4096
#define HEADS   8
#define DHEAD   128
#define ROWS    (BATCH*NQ)        // 9216
#define BHCNT   (BATCH*HEADS)     // 128

// ---------------- device scratch (no allocations allowed) ----------------
__device__ float g_kv[ROWS*DIM];
__device__ float g_kvpos[ROWS*DIM];
__device__ float g_qn[NQ*DIM];
__device__ float g_qp[NQ*DIM];
__device__ float g_kp[ROWS*DIM];
__device__ float g_vp[ROWS*DIM];
__device__ float g_sc[(size_t)BHCNT*NQ*NQ];   // 42.5M floats
__device__ float g_ctx[ROWS*DIM];
__device__ float g_attn[ROWS*DIM];
__device__ float g_h[(size_t)ROWS*HID];       // 37.7M floats
__device__ float g_gates[ROWS*2];
// tf32-pre-rounded operand copies
__device__ float g_xr[ROWS*DIM];
__device__ float g_w1r[(size_t)HID*DIM];
__device__ float g_w2r[(size_t)HID*HID];
__device__ float g_ipwr[(size_t)3*DIM*DIM];
__device__ float g_outwr[(size_t)DIM*DIM];

// ---------------- small helpers ----------------
__device__ __forceinline__ float warp_sum(float v){
    #pragma unroll
    for (int o=16;o;o>>=1) v += __shfl_xor_sync(0xffffffffu, v, o);
    return v;
}
__device__ __forceinline__ float softplusf(float x){
    return log1pf(expf(-fabsf(x))) + fmaxf(x, 0.f);
}
__device__ __forceinline__ float gelu_f(float x){
    return 0.5f * x * (1.0f + erff(x * 0.7071067811865475f));
}
__device__ __forceinline__ uint32_t f2tf(float x){
    uint32_t r; asm("cvt.rna.tf32.f32 %0, %1;" : "=r"(r) : "f"(x)); return r;
}
__device__ __forceinline__ float roundtf(float x){ return __uint_as_float(f2tf(x)); }
__device__ __forceinline__ void mma_tf32(float* c, const uint32_t* a, const uint32_t* b){
    asm volatile(
      "mma.sync.aligned.m16n8k8.row.col.f32.tf32.tf32.f32 "
      "{%0,%1,%2,%3}, {%4,%5,%6,%7}, {%8,%9}, {%0,%1,%2,%3};\n"
      : "+f"(c[0]), "+f"(c[1]), "+f"(c[2]), "+f"(c[3])
      : "r"(a[0]), "r"(a[1]), "r"(a[2]), "r"(a[3]), "r"(b[0]), "r"(b[1]));
}
__device__ __forceinline__ void cp_async16(void* smem, const void* gmem, int sz){
    uint32_t s = (uint32_t)__cvta_generic_to_shared(smem);
    asm volatile("cp.async.ca.shared.global [%0], [%1], 16, %2;\n"
                 :: "r"(s), "l"(gmem), "r"(sz));
}
__device__ __forceinline__ void cp_commit(){ asm volatile("cp.async.commit_group;\n"); }
__device__ __forceinline__ void cp_wait0(){ asm volatile("cp.async.wait_group 0;\n"); }

// ---------------- pre-round copy (fp32 -> tf32-rounded fp32) ----------------
__global__ void round_copy_kernel(const float4* __restrict__ in,
                                  float4* __restrict__ out, int n4)
{
    int i = blockIdx.x*blockDim.x + threadIdx.x;
    int stride = gridDim.x*blockDim.x;
    for (; i < n4; i += stride){
        float4 v = in[i];
        v.x = roundtf(v.x); v.y = roundtf(v.y);
        v.z = roundtf(v.z); v.w = roundtf(v.w);
        out[i] = v;
    }
}

// ---------------- LN(x) + pos + gating (fused: one read of x) ----------------
__global__ void ln_x_kernel(const float* __restrict__ x,
                            const float* __restrict__ g, const float* __restrict__ b,
                            const float* __restrict__ pos,
                            const float* __restrict__ wg, const float* __restrict__ wn,
                            const float* __restrict__ noise,
                            float* __restrict__ kv, float* __restrict__ kvpos,
                            float* __restrict__ gates)
{
    int row = blockIdx.x;
    int c   = row % NQ;
    const float* xr = x + (size_t)row*DIM;
    int t = threadIdx.x;
    float v[4];
    float s=0.f, ss=0.f, d0=0.f, d1=0.f, d2=0.f, d3=0.f;
    #pragma unroll
    for (int i=0;i<4;i++){
        int k = t + i*256;
        float xv = xr[k];
        v[i]=xv; s+=xv; ss+=xv*xv;
        d0 += xv*wg[k*2+0]; d1 += xv*wg[k*2+1];
        d2 += xv*wn[k*2+0]; d3 += xv*wn[k*2+1];
    }
    s  = warp_sum(s);  ss = warp_sum(ss);
    d0 = warp_sum(d0); d1 = warp_sum(d1);
    d2 = warp_sum(d2); d3 = warp_sum(d3);
    __shared__ float red[8][6];
    __shared__ float bc[2];
    int warp = t>>5, lane = t&31;
    if (lane==0){
        red[warp][0]=s; red[warp][1]=ss; red[warp][2]=d0;
        red[warp][3]=d1; red[warp][4]=d2; red[warp][5]=d3;
    }
    __syncthreads();
    if (t==0){
        float S=0,SS=0,D0=0,D1=0,D2=0,D3=0;
        #pragma unroll
        for (int w=0;w<8;w++){
            S+=red[w][0]; SS+=red[w][1]; D0+=red[w][2];
            D1+=red[w][3]; D2+=red[w][4]; D3+=red[w][5];
        }
        float mean = S * (1.f/DIM);
        float var  = SS * (1.f/DIM) - mean*mean;
        bc[0]=mean; bc[1]=rsqrtf(var + 1e-5f);
        float std0 = softplusf(D2) + 0.01f;
        float std1 = softplusf(D3) + 0.01f;
        float z0 = D0 + noise[(size_t)row*2+0]*std0;
        float z1 = D1 + noise[(size_t)row*2+1]*std1;
        float mz = fmaxf(z0,z1);
        float e0 = expf(z0-mz), e1 = expf(z1-mz);
        float l0 = e0/(e0+e1), l1 = e1/(e0+e1);
        float sm = l0 + l1;
        gates[(size_t)row*2+0] = l0/(sm+1e-6f);
        gates[(size_t)row*2+1] = l1/(sm+1e-6f);
    }
    __syncthreads();
    float mean = bc[0], inv = bc[1];
    #pragma unroll
    for (int i=0;i<4;i++){
        int k = t + i*256;
        float lnv = (v[i]-mean)*inv*g[k] + b[k];
        kv[(size_t)row*DIM + k]    = roundtf(lnv);
        kvpos[(size_t)row*DIM + k] = roundtf(lnv + pos[(size_t)c*DIM + k]);
    }
}

// ---------------- LN(query) + pos ----------------
__global__ void ln_q_kernel(const float* __restrict__ q,
                            const float* __restrict__ g, const float* __restrict__ b,
                            const float* __restrict__ pos, float* __restrict__ out)
{
    int row = blockIdx.x;
    const float* qr = q + (size_t)row*DIM;
    int t = threadIdx.x;
    float v[4];
    float s=0.f, ss=0.f;
    #pragma unroll
    for (int i=0;i<4;i++){
        int k = t + i*256;
        float xv = qr[k];
        v[i]=xv; s+=xv; ss+=xv*xv;
    }
    s = warp_sum(s); ss = warp_sum(ss);
    __shared__ float red[8][2];
    __shared__ float bc[2];
    int warp=t>>5, lane=t&31;
    if (lane==0){ red[warp][0]=s; red[warp][1]=ss; }
    __syncthreads();
    if (t==0){
        float S=0,SS=0;
        #pragma unroll
        for (int w=0;w<8;w++){ S+=red[w][0]; SS+=red[w][1]; }
        float mean = S*(1.f/DIM);
        float var  = SS*(1.f/DIM) - mean*mean;
        bc[0]=mean; bc[1]=rsqrtf(var+1e-5f);
    }
    __syncthreads();
    float mean=bc[0], inv=bc[1];
    #pragma unroll
    for (int i=0;i<4;i++){
        int k = t + i*256;
        out[(size_t)row*DIM + k] =
            roundtf((v[i]-mean)*inv*g[k] + b[k] + pos[(size_t)row*DIM + k]);
    }
}

// ---------------- row softmax over 576 cols (scale folded in) ----------------
__global__ void softmax_kernel(float* __restrict__ s){
    int warp = threadIdx.x>>5, lane = threadIdx.x&31;
    size_t row = (size_t)blockIdx.x*8 + warp;
    float* p = s + row*NQ;
    float v[18];
    float m = -1e30f;
    #pragma unroll
    for (int i=0;i<18;i++){ v[i] = p[lane + i*32]; m = fmaxf(m, v[i]); }
    #pragma unroll
    for (int o=16;o;o>>=1) m = fmaxf(m, __shfl_xor_sync(0xffffffffu, m, o));
    float sum = 0.f;
    const float SCALE = 0.08838834764831845f;   // 1/sqrt(128)
    #pragma unroll
    for (int i=0;i<18;i++){ v[i] = __expf((v[i]-m)*SCALE); sum += v[i]; }
    #pragma unroll
    for (int o=16;o;o>>=1) sum += __shfl_xor_sync(0xffffffffu, sum, o);
    float inv = 1.f/sum;
    #pragma unroll
    for (int i=0;i<18;i++) p[lane + i*32] = roundtf(v[i]*inv);
}

// ---------------- generic tf32 GEMM: C = epi(A(M,K) * B^T + bias) ----------------
// All gmem inputs are PRE-ROUNDED tf32 values; mainloop does raw-bit LDS -> mma.
// BT==0: B is (N,K) row-major (TN).  BT==1: B is (K,N) row-major (NN).
// EPI: 0=none 1=+bias 2=gelu(+bias) 3=g0*(+bias) write 4=+= g1*(+bias)
// EPI<=2 outputs feed later GEMMs -> stored tf32-rounded.
#define BMT 128
#define BNT 128
#define BKT 16
#define KPAD 20

template<int BT>
__device__ __forceinline__ void load_tile(
    float (*As)[KPAD], float (*Bs)[KPAD],
    const float* __restrict__ A, const float* __restrict__ Bm,
    int lda, int ldb, int m0, int n0, int M, int N, int k0, int tid)
{
    #pragma unroll
    for (int i=0;i<2;i++){
        int id = tid + i*256;
        int r = id >> 2, c4 = (id & 3)*4;
        int gr = m0 + r;
        int sz = (gr < M) ? 16 : 0;
        const float* src = A + (size_t)(gr < M ? gr : 0)*lda + k0 + c4;
        cp_async16(&As[r][c4], src, sz);
    }
    if (BT == 0){
        #pragma unroll
        for (int i=0;i<2;i++){
            int id = tid + i*256;
            int r = id >> 2, c4 = (id & 3)*4;
            int gr = n0 + r;
            int sz = (gr < N) ? 16 : 0;
            const float* src = Bm + (size_t)(gr < N ? gr : 0)*ldb + k0 + c4;
            cp_async16(&Bs[r][c4], src, sz);
        }
    } else {
        #pragma unroll
        for (int i=0;i<8;i++){
            int id = tid + i*256;
            int n = id & 127, k = id >> 7;
            int gn = n0 + n;
            float vv = 0.f;
            if (gn < N) vv = Bm[(size_t)(k0+k)*ldb + gn];
            Bs[n][k] = vv;
        }
    }
    cp_commit();
}

template<int EPI, int BT>
__global__ void __launch_bounds__(256,2) gemm_kernel(
    const float* __restrict__ A, int lda, long long aSB, long long aSH,
    const float* __restrict__ Bm, int ldb, long long bSB, long long bSH,
    const float* __restrict__ bias,
    float* __restrict__ C, int ldc, long long cSB, long long cSH,
    int M, int N, int K, int nh,
    const float* __restrict__ gates)
{
    __shared__ float As[2][BMT][KPAD];
    __shared__ float Bs[2][BNT][KPAD];
    int z = blockIdx.z;
    int hh = z % nh, bb = z / nh;
    A  += (size_t)bb*aSB + (size_t)hh*aSH;
    Bm += (size_t)bb*bSB + (size_t)hh*bSH;
    C  += (size_t)bb*cSB + (size_t)hh*cSH;
    int m0 = blockIdx.y*BMT, n0 = blockIdx.x*BNT;
    int tid = threadIdx.x;
    int warp = tid>>5, lane = tid&31;
    int wm = warp & 1, wn = warp >> 1;
    int group = lane>>2, tig = lane&3;
    int nK = K / BKT;

    float acc[4][4][4];
    #pragma unroll
    for (int a_=0;a_<4;a_++)
        #pragma unroll
        for (int b_=0;b_<4;b_++)
            #pragma unroll
            for (int c_=0;c_<4;c_++) acc[a_][b_][c_] = 0.f;

    load_tile<BT>(As[0], Bs[0], A, Bm, lda, ldb, m0, n0, M, N, 0, tid);

    for (int kt=0; kt<nK; kt++){
        cp_wait0();
        __syncthreads();
        if (kt+1 < nK)
            load_tile<BT>(As[(kt+1)&1], Bs[(kt+1)&1], A, Bm, lda, ldb,
                          m0, n0, M, N, (kt+1)*BKT, tid);
        const float (*as)[KPAD] = As[kt&1];
        const float (*bs)[KPAD] = Bs[kt&1];
        #pragma unroll
        for (int ks=0; ks<2; ks++){
            int kk = ks*8;
            uint32_t af[4][4], bf[4][2];
            #pragma unroll
            for (int mf=0; mf<4; mf++){
                int rA = wm*64 + mf*16;
                af[mf][0] = __float_as_uint(as[rA+group  ][kk+tig  ]);
                af[mf][1] = __float_as_uint(as[rA+group+8][kk+tig  ]);
                af[mf][2] = __float_as_uint(as[rA+group  ][kk+tig+4]);
                af[mf][3] = __float_as_uint(as[rA+group+8][kk+tig+4]);
            }
            #pragma unroll
            for (int nf=0; nf<4; nf++){
                int cB = wn*32 + nf*8;
                bf[nf][0] = __float_as_uint(bs[cB+group][kk+tig  ]);
                bf[nf][1] = __float_as_uint(bs[cB+group][kk+tig+4]);
            }
            #pragma unroll
            for (int mf=0; mf<4; mf++)
                #pragma unroll
                for (int nf=0; nf<4; nf++)
                    mma_tf32(acc[mf][nf], af[mf], bf[nf]);
        }
    }

    // epilogue
    #pragma unroll
    for (int mf=0; mf<4; mf++){
        #pragma unroll
        for (int half=0; half<2; half++){
            int r = m0 + wm*64 + mf*16 + group + half*8;
            if (r >= M) continue;
            float gv = 0.f;
            if (EPI==3) gv = gates[(size_t)r*2+0];
            if (EPI==4) gv = gates[(size_t)r*2+1];
            #pragma unroll
            for (int nf=0; nf<4; nf++){
                int col = n0 + wn*32 + nf*8 + tig*2;
                if (col >= N) continue;
                float v0 = acc[mf][nf][half*2+0];
                float v1 = acc[mf][nf][half*2+1];
                if (EPI >= 1){ v0 += bias[col]; v1 += bias[col+1]; }
                if (EPI == 2){ v0 = gelu_f(v0); v1 = gelu_f(v1); }
                float2* dst = reinterpret_cast<float2*>(C + (size_t)r*ldc + col);
                if (EPI == 3){ v0 *= gv; v1 *= gv; }
                if (EPI == 4){ float2 o = *dst; v0 = o.x + gv*v0; v1 = o.y + gv*v1; }
                if (EPI <= 2){ v0 = roundtf(v0); v1 = roundtf(v1); }
                float2 st; st.x = v0; st.y = v1;
                *dst = st;
            }
        }
    }
}

// ---------------- host launcher ----------------
extern "C" void kernel_launch(void* const* d_in, const int* in_sizes, int n_in,
                              void* d_out, int out_size)
{
    const float* x     = (const float*)d_in[0];
    const float* noise = (const float*)d_in[1];
    const float* W1    = (const float*)d_in[2];
    const float* b1    = (const float*)d_in[3];
    const float* W2    = (const float*)d_in[4];
    const float* b2    = (const float*)d_in[5];
    const float* query = (const float*)d_in[6];
    const float* pos   = (const float*)d_in[7];
    const float* lnqg  = (const float*)d_in[8];
    const float* lnqb  = (const float*)d_in[9];
    const float* lnkg  = (const float*)d_in[10];
    const float* lnkb  = (const float*)d_in[11];
    const float* ipw   = (const float*)d_in[12];
    const float* ipb   = (const float*)d_in[13];
    const float* outw  = (const float*)d_in[14];
    const float* outb  = (const float*)d_in[15];
    const float* wg    = (const float*)d_in[16];
    const float* wn    = (const float*)d_in[17];
    float* out = (float*)d_out;

    float *kv,*kvpos,*qn,*qp,*kp,*vp,*sc,*ctx,*attn,*hbuf,*gates;
    float *xr,*w1r,*w2r,*ipwr,*outwr;
    cudaGetSymbolAddress((void**)&kv,    g_kv);
    cudaGetSymbolAddress((void**)&kvpos, g_kvpos);
    cudaGetSymbolAddress((void**)&qn,    g_qn);
    cudaGetSymbolAddress((void**)&qp,    g_qp);
    cudaGetSymbolAddress((void**)&kp,    g_kp);
    cudaGetSymbolAddress((void**)&vp,    g_vp);
    cudaGetSymbolAddress((void**)&sc,    g_sc);
    cudaGetSymbolAddress((void**)&ctx,   g_ctx);
    cudaGetSymbolAddress((void**)&attn,  g_attn);
    cudaGetSymbolAddress((void**)&hbuf,  g_h);
    cudaGetSymbolAddress((void**)&gates, g_gates);
    cudaGetSymbolAddress((void**)&xr,    g_xr);
    cudaGetSymbolAddress((void**)&w1r,   g_w1r);
    cudaGetSymbolAddress((void**)&w2r,   g_w2r);
    cudaGetSymbolAddress((void**)&ipwr,  g_ipwr);
    cudaGetSymbolAddress((void**)&outwr, g_outwr);

    const long long SBH = (long long)NQ*NQ;           // 331776
    const long long SBB = (long long)HEADS*NQ*NQ;     // 2654208
    const long long KVB = (long long)NQ*DIM;          // 589824

    // 0) pre-round static operands to tf32 values (cheap, mostly overlapped)
    round_copy_kernel<<<2048,256>>>((const float4*)x,   (float4*)xr,   ROWS*DIM/4);
    round_copy_kernel<<<2048,256>>>((const float4*)W1,  (float4*)w1r,  HID*DIM/4);
    round_copy_kernel<<<4096,256>>>((const float4*)W2,  (float4*)w2r,  (int)((size_t)HID*HID/4));
    round_copy_kernel<<<2048,256>>>((const float4*)ipw, (float4*)ipwr, 3*DIM*DIM/4);
    round_copy_kernel<<<1024,256>>>((const float4*)outw,(float4*)outwr,DIM*DIM/4);

    // 1) LN(x) + pos + gating ; LN(query) + pos   (stores tf32-rounded)
    ln_x_kernel<<<ROWS, 256>>>(x, lnkg, lnkb, pos, wg, wn, noise, kv, kvpos, gates);
    ln_q_kernel<<<NQ, 256>>>(query, lnqg, lnqb, pos, qn);

    // 2) QKV projections
    gemm_kernel<1,0><<<dim3(8,5,1),256>>>(qn,DIM,0,0, ipwr,DIM,0,0, ipb,
                                          qp,DIM,0,0, NQ,DIM,DIM, 1, nullptr);
    gemm_kernel<1,0><<<dim3(8,72,1),256>>>(kvpos,DIM,0,0, ipwr+(size_t)DIM*DIM,DIM,0,0, ipb+DIM,
                                           kp,DIM,0,0, ROWS,DIM,DIM, 1, nullptr);
    gemm_kernel<1,0><<<dim3(8,72,1),256>>>(kv,DIM,0,0, ipwr+(size_t)2*DIM*DIM,DIM,0,0, ipb+2*DIM,
                                           vp,DIM,0,0, ROWS,DIM,DIM, 1, nullptr);

    // 3) attention: scores = qp @ kp^T (per batch*head), softmax, ctx = P @ vp
    gemm_kernel<0,0><<<dim3(5,5,BHCNT),256>>>(qp,DIM,0,DHEAD, kp,DIM,KVB,DHEAD, nullptr,
                                              sc,NQ, SBB,SBH, NQ,NQ,DHEAD, HEADS, nullptr);
    softmax_kernel<<<(BHCNT*NQ)/8, 256>>>(sc);
    gemm_kernel<0,1><<<dim3(1,5,BHCNT),256>>>(sc,NQ, SBB,SBH, vp,DIM,KVB,DHEAD, nullptr,
                                              ctx,DIM, KVB,DHEAD, NQ,DHEAD,NQ, HEADS, nullptr);

    // 4) attention output projection
    gemm_kernel<1,0><<<dim3(8,72,1),256>>>(ctx,DIM,0,0, outwr,DIM,0,0, outb,
                                           attn,DIM,0,0, ROWS,DIM,DIM, 1, nullptr);

    // 5) expert 0: gelu(x@W1^T+b1) @ W2^T + b2, scaled by g0 -> out
    gemm_kernel<2,0><<<dim3(32,72,1),256>>>(xr,DIM,0,0, w1r,DIM,0,0, b1,
                                            hbuf,HID,0,0, ROWS,HID,DIM, 1, nullptr);
    gemm_kernel<3,0><<<dim3(32,72,1),256>>>(hbuf,HID,0,0, w2r,HID,0,0, b2,
                                            out,HID,0,0, ROWS,HID,HID, 1, gates);

    // 6) expert 1: gelu(attn@W1^T+b1) @ W2^T + b2, scaled by g1, += out
    gemm_kernel<2,0><<<dim3(32,72,1),256>>>(attn,DIM,0,0, w1r,DIM,0,0, b1,
                                            hbuf,HID,0,0, ROWS,HID,DIM, 1, nullptr);
    gemm_kernel<4,0><<<dim3(32,72,1),256>>>(hbuf,HID,0,0, w2r,HID,0,0, b2,
                                            out,HID,0,0, ROWS,HID,HID, 1, gates);
}